// round 4
// baseline (speedup 1.0000x reference)
#include <cuda_runtime.h>
#include <cuda_fp16.h>
#include <mma.h>
#include <cstdint>

// Problem shape (fixed by this problem instance)
#define HDIM 256   // input features
#define HMID 128   // hidden
#define ODIM 128   // output features
#define TILE 128   // rows per CTA

#define NEG_SLOPE 0.015f

// smem layout (bytes)
//  Phase A: sA   [128 x 272] half  @ 0       (69,632)
//           sW1  [256 x 144] half  @ 69,632  (73,728)  -> end 143,360
//  Phase B: sC   [128 x 132] f32   @ 0       (67,584)
//           sW2  [128 x 144] half  @ 69,632  (36,864)  -> end 106,496
//           sH   [128 x 144] half  @ 106,496 (36,864)  -> end 143,360
//  Always:  sIdx [128] int         @ 143,360 (512)     -> total 143,872
#define OFF_A   0
#define OFF_W1  69632
#define OFF_C   0
#define OFF_W2  69632
#define OFF_H   106496
#define OFF_IDX 143360
#define SMEM_BYTES 143872

#define LDA 272   // half elems
#define LDW 144   // half elems
#define LDC 132   // f32 elems

__device__ int g_is64;
__device__ int g_cnt[65536];

// ---------------------------------------------------------------------------
// Detect whether batch is int64 or int32.
// View buffer as int32 words. If int64 (LE), words are v0,0,v1,0,... -> a
// sampled pair (w[2k] > w[2k+1]) exists once values > 0. If int32 the sorted
// sequence is non-decreasing -> no such pair. All-zero case: identical ids.
// ---------------------------------------------------------------------------
__global__ void detect_kernel(const int* __restrict__ w, long long nwords) {
    __shared__ int flag;
    if (threadIdx.x == 0) flag = 0;
    __syncthreads();
    long long half = nwords >> 1;
    long long step = (half > 257) ? (half - 1) / 256 : 1;
    long long k = (long long)threadIdx.x * step;
    if (2 * k + 1 < nwords) {
        if (w[2 * k] > w[2 * k + 1]) atomicOr(&flag, 1);
    }
    __syncthreads();
    if (threadIdx.x == 0) g_is64 = flag;
}

__device__ __forceinline__ long long get_batch(const void* p, long long i, int is64) {
    return is64 ? ((const long long*)p)[i] : (long long)((const int*)p)[i];
}

// Per-group count via binary search over sorted batch ids.
__global__ void counts_kernel(const void* __restrict__ batch, long long n, int G) {
    int g = blockIdx.x * blockDim.x + threadIdx.x;
    if (g >= G || g >= 65536) return;
    int is64 = g_is64;
    long long lo = 0, hi = n;
    while (lo < hi) { long long m = (lo + hi) >> 1; if (get_batch(batch, m, is64) < g) lo = m + 1; else hi = m; }
    long long lb = lo;
    hi = n;
    while (lo < hi) { long long m = (lo + hi) >> 1; if (get_batch(batch, m, is64) <= g) lo = m + 1; else hi = m; }
    g_cnt[g] = (int)(lo - lb);
}

__global__ void zero_kernel(float* __restrict__ out, long long n) {
    long long i = (long long)blockIdx.x * blockDim.x + threadIdx.x;
    if (i < n) out[i] = 0.0f;
}

__global__ void divide_kernel(float* __restrict__ out, long long n) {
    long long i = (long long)blockIdx.x * blockDim.x + threadIdx.x;
    if (i >= n) return;
    int g = (int)(i >> 7);  // ODIM = 128
    int c = (g < 65536) ? g_cnt[g] : 0;
    float d = (c > 0) ? (float)c : 1.0f;
    out[i] /= d;
}

// ---------------------------------------------------------------------------
// Fused: h1 = leaky(v@W1 + b1); h2 = h1@W2 + b2; segment-sum h2 into out.
// One CTA handles TILE=128 contiguous rows. 256 threads = 8 warps, warp grid
// 4x2 over the 128x128 output (each warp: 32 rows x 64 cols = 2x4 wmma tiles).
// fp16 operands (11-bit significand), fp32 accumulation.
// ---------------------------------------------------------------------------
__global__ void __launch_bounds__(256)
mlp_kernel(const float* __restrict__ v, const void* __restrict__ batch,
           const float* __restrict__ W1, const float* __restrict__ b1,
           const float* __restrict__ W2, const float* __restrict__ b2,
           float* __restrict__ out, long long N) {
    extern __shared__ char smem[];
    __half* sA  = (__half*)(smem + OFF_A);
    __half* sW1 = (__half*)(smem + OFF_W1);
    float*  sC  = (float*)(smem + OFF_C);
    __half* sW2 = (__half*)(smem + OFF_W2);
    __half* sH  = (__half*)(smem + OFF_H);
    int*    sIdx = (int*)(smem + OFF_IDX);

    const int tid = threadIdx.x;
    const long long r0 = (long long)blockIdx.x * TILE;
    const int is64 = g_is64;

    // --- load v tile (contiguous 128*256 floats) -> fp16 smem ---
    {
        const float4* src = (const float4*)(v + r0 * HDIM);
        #pragma unroll
        for (int it = 0; it < 32; ++it) {
            int l4 = it * 256 + tid;           // float4 index within tile
            int row = (l4 * 4) / HDIM;
            int col = (l4 * 4) % HDIM;
            float4 f = make_float4(0.f, 0.f, 0.f, 0.f);
            if (r0 + row < N) f = src[l4];
            __half* d = &sA[row * LDA + col];
            d[0] = __float2half(f.x); d[1] = __float2half(f.y);
            d[2] = __float2half(f.z); d[3] = __float2half(f.w);
        }
    }
    // --- load W1 (256x128) -> fp16 smem ---
    {
        const float4* src = (const float4*)W1;
        #pragma unroll
        for (int it = 0; it < 32; ++it) {
            int l4 = it * 256 + tid;
            float4 f = src[l4];
            int row = (l4 * 4) / HMID;
            int col = (l4 * 4) % HMID;
            __half* d = &sW1[row * LDW + col];
            d[0] = __float2half(f.x); d[1] = __float2half(f.y);
            d[2] = __float2half(f.z); d[3] = __float2half(f.w);
        }
    }
    // --- batch ids for this tile ---
    if (tid < TILE) {
        long long r = r0 + tid;
        int g = -1;
        if (r < N) g = (int)get_batch(batch, r, is64);
        sIdx[tid] = g;
    }
    __syncthreads();

    using namespace nvcuda;
    const int warpId = tid >> 5;
    const int wm = warpId >> 1;   // 0..3 (32-row band)
    const int wn = warpId & 1;    // 0..1 (64-col band)

    wmma::fragment<wmma::accumulator, 16, 16, 16, float> acc[2][4];

    // --- GEMM1: C = A[128x256] @ W1[256x128] ---
    #pragma unroll
    for (int i = 0; i < 2; ++i)
        #pragma unroll
        for (int j = 0; j < 4; ++j) wmma::fill_fragment(acc[i][j], 0.0f);

    #pragma unroll
    for (int k = 0; k < HDIM / 16; ++k) {
        wmma::fragment<wmma::matrix_a, 16, 16, 16, __half, wmma::row_major> af[2];
        #pragma unroll
        for (int i = 0; i < 2; ++i)
            wmma::load_matrix_sync(af[i], &sA[(wm * 32 + i * 16) * LDA + k * 16], LDA);
        wmma::fragment<wmma::matrix_b, 16, 16, 16, __half, wmma::row_major> bf[4];
        #pragma unroll
        for (int j = 0; j < 4; ++j)
            wmma::load_matrix_sync(bf[j], &sW1[(k * 16) * LDW + wn * 64 + j * 16], LDW);
        #pragma unroll
        for (int i = 0; i < 2; ++i)
            #pragma unroll
            for (int j = 0; j < 4; ++j)
                wmma::mma_sync(acc[i][j], af[i], bf[j], acc[i][j]);
    }
    __syncthreads();  // done reading sA/sW1

    // store C1 (f32) to smem; concurrently stage W2 as fp16
    #pragma unroll
    for (int i = 0; i < 2; ++i)
        #pragma unroll
        for (int j = 0; j < 4; ++j)
            wmma::store_matrix_sync(&sC[(wm * 32 + i * 16) * LDC + wn * 64 + j * 16],
                                    acc[i][j], LDC, wmma::mem_row_major);
    {
        const float4* src = (const float4*)W2;
        #pragma unroll
        for (int it = 0; it < 16; ++it) {
            int l4 = it * 256 + tid;
            float4 f = src[l4];
            int row = (l4 * 4) / ODIM;
            int col = (l4 * 4) % ODIM;
            __half* d = &sW2[row * LDW + col];
            d[0] = __float2half(f.x); d[1] = __float2half(f.y);
            d[2] = __float2half(f.z); d[3] = __float2half(f.w);
        }
    }
    __syncthreads();

    // --- bias + LeakyReLU + convert -> sH (fp16) ---
    #pragma unroll
    for (int it = 0; it < 64; ++it) {
        int l = it * 256 + tid;
        int row = l >> 7;
        int col = l & 127;
        float x = sC[row * LDC + col] + b1[col];
        x = (x >= 0.f) ? x : NEG_SLOPE * x;
        sH[row * LDW + col] = __float2half(x);
    }
    __syncthreads();

    // --- GEMM2: C = H[128x128] @ W2[128x128] ---
    #pragma unroll
    for (int i = 0; i < 2; ++i)
        #pragma unroll
        for (int j = 0; j < 4; ++j) wmma::fill_fragment(acc[i][j], 0.0f);

    #pragma unroll
    for (int k = 0; k < HMID / 16; ++k) {
        wmma::fragment<wmma::matrix_a, 16, 16, 16, __half, wmma::row_major> af[2];
        #pragma unroll
        for (int i = 0; i < 2; ++i)
            wmma::load_matrix_sync(af[i], &sH[(wm * 32 + i * 16) * LDW + k * 16], LDW);
        wmma::fragment<wmma::matrix_b, 16, 16, 16, __half, wmma::row_major> bf[4];
        #pragma unroll
        for (int j = 0; j < 4; ++j)
            wmma::load_matrix_sync(bf[j], &sW2[(k * 16) * LDW + wn * 64 + j * 16], LDW);
        #pragma unroll
        for (int i = 0; i < 2; ++i)
            #pragma unroll
            for (int j = 0; j < 4; ++j)
                wmma::mma_sync(acc[i][j], af[i], bf[j], acc[i][j]);
    }
    __syncthreads();  // everyone done reading sH/sW2; sC free

    #pragma unroll
    for (int i = 0; i < 2; ++i)
        #pragma unroll
        for (int j = 0; j < 4; ++j)
            wmma::store_matrix_sync(&sC[(wm * 32 + i * 16) * LDC + wn * 64 + j * 16],
                                    acc[i][j], LDC, wmma::mem_row_major);
    __syncthreads();

    // --- segment accumulate: run-length compress sorted group ids ---
    {
        int c = tid & 127;        // column
        int half = tid >> 7;      // 0/1: rows [0,64) or [64,128)
        float b2c = b2[c];
        int rbeg = half * 64, rend = rbeg + 64;
        int curg = sIdx[rbeg];
        float s = 0.0f;
        for (int i = rbeg; i < rend; ++i) {
            int g = sIdx[i];
            float val = sC[i * LDC + c] + b2c;
            if (g != curg) {
                if (curg >= 0) atomicAdd(&out[(long long)curg * ODIM + c], s);
                curg = g; s = 0.0f;
            }
            if (g >= 0) s += val;
        }
        if (curg >= 0) atomicAdd(&out[(long long)curg * ODIM + c], s);
    }
}

// ---------------------------------------------------------------------------
extern "C" void kernel_launch(void* const* d_in, const int* in_sizes, int n_in,
                              void* d_out, int out_size) {
    // metadata order: v, batch, num_graphs, W1, b1, W2, b2
    const float* v     = (const float*)d_in[0];
    const void*  batch = d_in[1];
    const float* W1    = (const float*)d_in[3];
    const float* b1    = (const float*)d_in[4];
    const float* W2    = (const float*)d_in[5];
    const float* b2    = (const float*)d_in[6];
    float* out = (float*)d_out;

    long long N = (long long)in_sizes[1];            // rows
    long long OUT = (long long)out_size;             // G * ODIM
    int G = (int)(OUT / ODIM);

    cudaFuncSetAttribute(mlp_kernel, cudaFuncAttributeMaxDynamicSharedMemorySize, 147456);

    detect_kernel<<<1, 256>>>((const int*)batch, N);
    counts_kernel<<<(G + 255) / 256, 256>>>(batch, N, G);
    zero_kernel<<<(unsigned)((OUT + 255) / 256), 256>>>(out, OUT);

    unsigned nblocks = (unsigned)((N + TILE - 1) / TILE);
    mlp_kernel<<<nblocks, 256, SMEM_BYTES>>>(v, batch, W1, b1, W2, b2, out, N);

    divide_kernel<<<(unsigned)((OUT + 255) / 256), 256>>>(out, OUT);
}

// round 5
// speedup vs baseline: 1.1356x; 1.1356x over previous
#include <cuda_runtime.h>
#include <cuda_fp16.h>
#include <mma.h>
#include <cstdint>

// Problem shape (fixed by this problem instance)
#define HDIM 256   // input features
#define HMID 128   // hidden
#define ODIM 128   // output features
#define TILE 128   // rows per tile

#define NEG_SLOPE 0.015f

// Persistent smem layout (bytes):
//  sW1  [256 x 136] half @ 0        (69,632)   persistent
//  sW2  [128 x 136] half @ 69,632   (34,816)   persistent -> 104,448
//  sB1  [128] f32        @ 104,448  (512)      persistent -> 104,960
//  sB2  [128] f32        @ 104,960  (512)      persistent -> 105,472
//  sA   [128 x 264] half @ 105,472  (67,584)   per-tile v tile (fp16)
//  sC   [128 x 132] f32  @ 105,472  (67,584)   overlays sA (sA dead after GEMM1)
//  sH   [128 x 136] half @ 173,056  (34,816)   hidden activations
//  sIdx [128] int        @ 207,872  (512)      -> total 208,384
#define OFF_W1  0
#define OFF_W2  69632
#define OFF_B1  104448
#define OFF_B2  104960
#define OFF_A   105472
#define OFF_C   105472
#define OFF_H   173056
#define OFF_IDX 207872
#define SMEM_BYTES 208384

#define LDA 264   // half elems
#define LDW 136   // half elems
#define LDC 132   // f32 elems

__device__ int g_is64;
__device__ int g_cnt[65536];

// ---------------------------------------------------------------------------
// Detect whether batch is int64 or int32 (sorted, non-negative ids).
// View as int32 words: int64 LE gives v0,0,v1,0,... -> some w[2k] > w[2k+1]
// once values > 0; sorted int32 is non-decreasing -> never. All-zero: same ids.
// ---------------------------------------------------------------------------
__global__ void detect_kernel(const int* __restrict__ w, long long nwords) {
    __shared__ int flag;
    if (threadIdx.x == 0) flag = 0;
    __syncthreads();
    long long half = nwords >> 1;
    long long step = (half > 257) ? (half - 1) / 256 : 1;
    long long k = (long long)threadIdx.x * step;
    if (2 * k + 1 < nwords) {
        if (w[2 * k] > w[2 * k + 1]) atomicOr(&flag, 1);
    }
    __syncthreads();
    if (threadIdx.x == 0) g_is64 = flag;
}

__device__ __forceinline__ long long get_batch(const void* p, long long i, int is64) {
    return is64 ? ((const long long*)p)[i] : (long long)((const int*)p)[i];
}

// Per-group count via binary search over sorted batch ids.
__global__ void counts_kernel(const void* __restrict__ batch, long long n, int G) {
    int g = blockIdx.x * blockDim.x + threadIdx.x;
    if (g >= G || g >= 65536) return;
    int is64 = g_is64;
    long long lo = 0, hi = n;
    while (lo < hi) { long long m = (lo + hi) >> 1; if (get_batch(batch, m, is64) < g) lo = m + 1; else hi = m; }
    long long lb = lo;
    hi = n;
    while (lo < hi) { long long m = (lo + hi) >> 1; if (get_batch(batch, m, is64) <= g) lo = m + 1; else hi = m; }
    g_cnt[g] = (int)(lo - lb);
}

__global__ void zero_kernel(float* __restrict__ out, long long n) {
    long long i = (long long)blockIdx.x * blockDim.x + threadIdx.x;
    if (i < n) out[i] = 0.0f;
}

__global__ void divide_kernel(float* __restrict__ out, long long n) {
    long long i = (long long)blockIdx.x * blockDim.x + threadIdx.x;
    if (i >= n) return;
    int g = (int)(i >> 7);  // ODIM = 128
    int c = (g < 65536) ? g_cnt[g] : 0;
    float d = (c > 0) ? (float)c : 1.0f;
    out[i] /= d;
}

// ---------------------------------------------------------------------------
// Persistent fused kernel. Each CTA stages W1/W2/b1/b2 into smem ONCE, then
// grid-strides over 128-row tiles:
//   h1 = leaky(v@W1 + b1); h2 = h1@W2 + b2; segment-sum h2 into out.
// 256 threads = 8 warps as a 4x2 grid over the 128x128 output
// (each warp: 32 rows x 64 cols = 2x4 wmma m16n16k16 tiles).
// fp16 operands, fp32 accumulation.
// ---------------------------------------------------------------------------
__global__ void __launch_bounds__(256)
mlp_kernel(const float* __restrict__ v, const void* __restrict__ batch,
           const float* __restrict__ W1, const float* __restrict__ b1,
           const float* __restrict__ W2, const float* __restrict__ b2,
           float* __restrict__ out, long long N, long long ntiles) {
    extern __shared__ char smem[];
    __half* sW1 = (__half*)(smem + OFF_W1);
    __half* sW2 = (__half*)(smem + OFF_W2);
    float*  sB1 = (float*)(smem + OFF_B1);
    float*  sB2 = (float*)(smem + OFF_B2);
    __half* sA  = (__half*)(smem + OFF_A);
    float*  sC  = (float*)(smem + OFF_C);
    __half* sH  = (__half*)(smem + OFF_H);
    int*    sIdx = (int*)(smem + OFF_IDX);

    const int tid = threadIdx.x;
    const int is64 = g_is64;

    // ---- one-time weight staging (f32 global -> f16 smem) ----
    {
        const float4* src = (const float4*)W1;   // 256x128 = 8192 float4
        #pragma unroll
        for (int it = 0; it < 32; ++it) {
            int l4 = it * 256 + tid;
            float4 f = src[l4];
            int row = (l4 * 4) / HMID;
            int col = (l4 * 4) % HMID;
            __half* d = &sW1[row * LDW + col];
            d[0] = __float2half(f.x); d[1] = __float2half(f.y);
            d[2] = __float2half(f.z); d[3] = __float2half(f.w);
        }
        const float4* src2 = (const float4*)W2;  // 128x128 = 4096 float4
        #pragma unroll
        for (int it = 0; it < 16; ++it) {
            int l4 = it * 256 + tid;
            float4 f = src2[l4];
            int row = (l4 * 4) / ODIM;
            int col = (l4 * 4) % ODIM;
            __half* d = &sW2[row * LDW + col];
            d[0] = __float2half(f.x); d[1] = __float2half(f.y);
            d[2] = __float2half(f.z); d[3] = __float2half(f.w);
        }
        if (tid < 128) { sB1[tid] = b1[tid]; sB2[tid] = b2[tid]; }
    }

    using namespace nvcuda;
    const int warpId = tid >> 5;
    const int wm = warpId >> 1;   // 0..3 (32-row band)
    const int wn = warpId & 1;    // 0..1 (64-col band)

    for (long long tile = blockIdx.x; tile < ntiles; tile += gridDim.x) {
        const long long r0 = tile * TILE;

        // protects sA/sC region against previous iteration's atomic phase,
        // and (first iteration) orders weight staging before use
        __syncthreads();

        // --- load v tile (128*256 f32, contiguous) -> fp16 sA ---
        {
            const float4* src = (const float4*)(v + r0 * HDIM);
            #pragma unroll
            for (int it = 0; it < 32; ++it) {
                int l4 = it * 256 + tid;           // float4 index within tile
                int row = (l4 * 4) / HDIM;
                int col = (l4 * 4) % HDIM;
                float4 f = make_float4(0.f, 0.f, 0.f, 0.f);
                if (r0 + row < N) f = src[l4];
                __half* d = &sA[row * LDA + col];
                d[0] = __float2half(f.x); d[1] = __float2half(f.y);
                d[2] = __float2half(f.z); d[3] = __float2half(f.w);
            }
        }
        if (tid < TILE) {
            long long r = r0 + tid;
            int g = -1;
            if (r < N) g = (int)get_batch(batch, r, is64);
            sIdx[tid] = g;
        }
        __syncthreads();

        wmma::fragment<wmma::accumulator, 16, 16, 16, float> acc[2][4];

        // --- GEMM1: C1 = A[128x256] @ W1[256x128] ---
        #pragma unroll
        for (int i = 0; i < 2; ++i)
            #pragma unroll
            for (int j = 0; j < 4; ++j) wmma::fill_fragment(acc[i][j], 0.0f);

        #pragma unroll
        for (int k = 0; k < HDIM / 16; ++k) {
            wmma::fragment<wmma::matrix_a, 16, 16, 16, __half, wmma::row_major> af[2];
            #pragma unroll
            for (int i = 0; i < 2; ++i)
                wmma::load_matrix_sync(af[i], &sA[(wm * 32 + i * 16) * LDA + k * 16], LDA);
            wmma::fragment<wmma::matrix_b, 16, 16, 16, __half, wmma::row_major> bf[4];
            #pragma unroll
            for (int j = 0; j < 4; ++j)
                wmma::load_matrix_sync(bf[j], &sW1[(k * 16) * LDW + wn * 64 + j * 16], LDW);
            #pragma unroll
            for (int i = 0; i < 2; ++i)
                #pragma unroll
                for (int j = 0; j < 4; ++j)
                    wmma::mma_sync(acc[i][j], af[i], bf[j], acc[i][j]);
        }
        __syncthreads();  // all warps done reading sA -> safe to overlay with sC

        #pragma unroll
        for (int i = 0; i < 2; ++i)
            #pragma unroll
            for (int j = 0; j < 4; ++j)
                wmma::store_matrix_sync(&sC[(wm * 32 + i * 16) * LDC + wn * 64 + j * 16],
                                        acc[i][j], LDC, wmma::mem_row_major);
        __syncthreads();

        // --- bias + LeakyReLU + convert -> sH (fp16) ---
        #pragma unroll
        for (int it = 0; it < 64; ++it) {
            int l = it * 256 + tid;
            int row = l >> 7;
            int col = l & 127;
            float x = sC[row * LDC + col] + sB1[col];
            x = (x >= 0.f) ? x : NEG_SLOPE * x;
            sH[row * LDW + col] = __float2half(x);
        }
        __syncthreads();

        // --- GEMM2: C2 = H[128x128] @ W2[128x128] ---
        #pragma unroll
        for (int i = 0; i < 2; ++i)
            #pragma unroll
            for (int j = 0; j < 4; ++j) wmma::fill_fragment(acc[i][j], 0.0f);

        #pragma unroll
        for (int k = 0; k < HMID / 16; ++k) {
            wmma::fragment<wmma::matrix_a, 16, 16, 16, __half, wmma::row_major> af[2];
            #pragma unroll
            for (int i = 0; i < 2; ++i)
                wmma::load_matrix_sync(af[i], &sH[(wm * 32 + i * 16) * LDW + k * 16], LDW);
            wmma::fragment<wmma::matrix_b, 16, 16, 16, __half, wmma::row_major> bf[4];
            #pragma unroll
            for (int j = 0; j < 4; ++j)
                wmma::load_matrix_sync(bf[j], &sW2[(k * 16) * LDW + wn * 64 + j * 16], LDW);
            #pragma unroll
            for (int i = 0; i < 2; ++i)
                #pragma unroll
                for (int j = 0; j < 4; ++j)
                    wmma::mma_sync(acc[i][j], af[i], bf[j], acc[i][j]);
        }
        // sC region is dead (bias pass ended at a sync); each warp writes its
        // own C2 block — no cross-warp hazard with sH reads still in flight.
        #pragma unroll
        for (int i = 0; i < 2; ++i)
            #pragma unroll
            for (int j = 0; j < 4; ++j)
                wmma::store_matrix_sync(&sC[(wm * 32 + i * 16) * LDC + wn * 64 + j * 16],
                                        acc[i][j], LDC, wmma::mem_row_major);
        __syncthreads();

        // --- segment accumulate: run-length compress sorted group ids ---
        {
            int c = tid & 127;        // column
            int half = tid >> 7;      // 0/1: rows [0,64) or [64,128)
            float b2c = sB2[c];
            int rbeg = half * 64, rend = rbeg + 64;
            int curg = sIdx[rbeg];
            float s = 0.0f;
            for (int i = rbeg; i < rend; ++i) {
                int g = sIdx[i];
                float val = sC[i * LDC + c] + b2c;
                if (g != curg) {
                    if (curg >= 0) atomicAdd(&out[(long long)curg * ODIM + c], s);
                    curg = g; s = 0.0f;
                }
                if (g >= 0) s += val;
            }
            if (curg >= 0) atomicAdd(&out[(long long)curg * ODIM + c], s);
        }
    }
}

// ---------------------------------------------------------------------------
extern "C" void kernel_launch(void* const* d_in, const int* in_sizes, int n_in,
                              void* d_out, int out_size) {
    // metadata order: v, batch, num_graphs, W1, b1, W2, b2
    const float* v     = (const float*)d_in[0];
    const void*  batch = d_in[1];
    const float* W1    = (const float*)d_in[3];
    const float* b1    = (const float*)d_in[4];
    const float* W2    = (const float*)d_in[5];
    const float* b2    = (const float*)d_in[6];
    float* out = (float*)d_out;

    long long N = (long long)in_sizes[1];            // rows
    long long OUT = (long long)out_size;             // G * ODIM
    int G = (int)(OUT / ODIM);
    long long ntiles = (N + TILE - 1) / TILE;

    int dev = 0, nsm = 148;
    cudaGetDevice(&dev);
    cudaDeviceGetAttribute(&nsm, cudaDevAttrMultiProcessorCount, dev);
    long long grid = (ntiles < (long long)nsm) ? ntiles : (long long)nsm;

    cudaFuncSetAttribute(mlp_kernel, cudaFuncAttributeMaxDynamicSharedMemorySize, 232448);

    detect_kernel<<<1, 256>>>((const int*)batch, N);
    counts_kernel<<<(G + 255) / 256, 256>>>(batch, N, G);
    zero_kernel<<<(unsigned)((OUT + 255) / 256), 256>>>(out, OUT);

    mlp_kernel<<<(unsigned)grid, 256, SMEM_BYTES>>>(v, batch, W1, b1, W2, b2, out, N, ntiles);

    divide_kernel<<<(unsigned)((OUT + 255) / 256), 256>>>(out, OUT);
}

// round 6
// speedup vs baseline: 1.4792x; 1.3026x over previous
#include <cuda_runtime.h>
#include <cuda_fp16.h>
#include <mma.h>
#include <cstdint>

// Problem shape (fixed by this problem instance)
#define HDIM 256   // input features
#define HMID 128   // hidden
#define ODIM 128   // output features
#define TILE 128   // rows per tile
#define THREADS 512

#define NEG_SLOPE 0.015f

// Persistent smem layout (bytes):
//  sW1  [256 x 136] half @ 0        (69,632)   persistent
//  sW2  [128 x 136] half @ 69,632   (34,816)   persistent -> 104,448
//  sB1  [128] f32        @ 104,448  (512)      -> 104,960
//  sB2  [128] f32        @ 104,960  (512)      -> 105,472
//  sBuf (unified)        @ 105,472  (67,584)   -> 173,056
//       as sA: [128 x 264] half (v tile)
//       as sC: [128 x 132] f32  (GEMM1 / GEMM2 accum)
//       as sH: [128 x 264-stride] half (hidden, first 256B of each 528B row)
//  sIdx [128] int        @ 173,056  (512)      -> total 173,568
#define OFF_W1  0
#define OFF_W2  69632
#define OFF_B1  104448
#define OFF_B2  104960
#define OFF_BUF 105472
#define OFF_IDX 173056
#define SMEM_BYTES 173568

#define LDA 264   // half elems (528 B = 33*16B, conflict-friendly)
#define LDW 136   // half elems (272 B = 17*16B)
#define LDC 132   // f32 elems  (528 B)

__device__ int g_is64;
__device__ int g_cnt[65536];

// ---------------------------------------------------------------------------
// Detect whether batch is int64 or int32 (sorted, non-negative ids).
// ---------------------------------------------------------------------------
__global__ void detect_kernel(const int* __restrict__ w, long long nwords) {
    __shared__ int flag;
    if (threadIdx.x == 0) flag = 0;
    __syncthreads();
    long long half = nwords >> 1;
    long long step = (half > 257) ? (half - 1) / 256 : 1;
    long long k = (long long)threadIdx.x * step;
    if (2 * k + 1 < nwords) {
        if (w[2 * k] > w[2 * k + 1]) atomicOr(&flag, 1);
    }
    __syncthreads();
    if (threadIdx.x == 0) g_is64 = flag;
}

__device__ __forceinline__ long long get_batch(const void* p, long long i, int is64) {
    return is64 ? ((const long long*)p)[i] : (long long)((const int*)p)[i];
}

__global__ void counts_kernel(const void* __restrict__ batch, long long n, int G) {
    int g = blockIdx.x * blockDim.x + threadIdx.x;
    if (g >= G || g >= 65536) return;
    int is64 = g_is64;
    long long lo = 0, hi = n;
    while (lo < hi) { long long m = (lo + hi) >> 1; if (get_batch(batch, m, is64) < g) lo = m + 1; else hi = m; }
    long long lb = lo;
    hi = n;
    while (lo < hi) { long long m = (lo + hi) >> 1; if (get_batch(batch, m, is64) <= g) lo = m + 1; else hi = m; }
    g_cnt[g] = (int)(lo - lb);
}

__global__ void zero_kernel(float* __restrict__ out, long long n) {
    long long i = (long long)blockIdx.x * blockDim.x + threadIdx.x;
    if (i < n) out[i] = 0.0f;
}

__global__ void divide_kernel(float* __restrict__ out, long long n) {
    long long i = (long long)blockIdx.x * blockDim.x + threadIdx.x;
    if (i >= n) return;
    int g = (int)(i >> 7);  // ODIM = 128
    int c = (g < 65536) ? g_cnt[g] : 0;
    float d = (c > 0) ? (float)c : 1.0f;
    out[i] /= d;
}

// ---------------------------------------------------------------------------
// Persistent fused kernel, 512 threads = 16 warps (4/SMSP).
// Warp grid 4x4 over the 128x128 output; each warp owns 32x32 (2x2 wmma
// m16n16k16 tiles). One unified per-tile smem buffer cycles through:
// f16 v-tile -> f32 C1 -> (in-place, reg-staged) f16 H -> f32 C2.
// ---------------------------------------------------------------------------
__global__ void __launch_bounds__(THREADS)
mlp_kernel(const float* __restrict__ v, const void* __restrict__ batch,
           const float* __restrict__ W1, const float* __restrict__ b1,
           const float* __restrict__ W2, const float* __restrict__ b2,
           float* __restrict__ out, long long N, long long ntiles) {
    extern __shared__ char smem[];
    __half* sW1 = (__half*)(smem + OFF_W1);
    __half* sW2 = (__half*)(smem + OFF_W2);
    float*  sB1 = (float*)(smem + OFF_B1);
    float*  sB2 = (float*)(smem + OFF_B2);
    __half* sA  = (__half*)(smem + OFF_BUF);
    float*  sC  = (float*)(smem + OFF_BUF);
    float2* sC2 = (float2*)(smem + OFF_BUF);   // [128 x 66]
    __half2* sH2 = (__half2*)(smem + OFF_BUF); // [128 x 132] (stride 132 half2)
    __half* sH  = (__half*)(smem + OFF_BUF);   // stride LDA halves
    int*    sIdx = (int*)(smem + OFF_IDX);

    const int tid = threadIdx.x;
    const int is64 = g_is64;

    // ---- one-time weight + bias staging (f32 global -> f16/f32 smem) ----
    {
        const float4* src = (const float4*)W1;   // 256x128 = 8192 float4
        #pragma unroll
        for (int it = 0; it < 16; ++it) {
            int l4 = it * THREADS + tid;
            float4 f = src[l4];
            int row = (l4 * 4) / HMID;
            int col = (l4 * 4) % HMID;
            __half* d = &sW1[row * LDW + col];
            d[0] = __float2half(f.x); d[1] = __float2half(f.y);
            d[2] = __float2half(f.z); d[3] = __float2half(f.w);
        }
        const float4* src2 = (const float4*)W2;  // 128x128 = 4096 float4
        #pragma unroll
        for (int it = 0; it < 8; ++it) {
            int l4 = it * THREADS + tid;
            float4 f = src2[l4];
            int row = (l4 * 4) / ODIM;
            int col = (l4 * 4) % ODIM;
            __half* d = &sW2[row * LDW + col];
            d[0] = __float2half(f.x); d[1] = __float2half(f.y);
            d[2] = __float2half(f.z); d[3] = __float2half(f.w);
        }
        if (tid < 128) { sB1[tid] = b1[tid]; sB2[tid] = b2[tid]; }
    }
    __syncthreads();

    // Per-thread constant column assignments (512 == 0 mod 64/128):
    const int col2 = tid & 63;          // half2 column for conversion pass
    const float2 bb1 = make_float2(sB1[2 * col2], sB1[2 * col2 + 1]);
    const int segc = tid & 127;         // column for segment pass
    const int segq = tid >> 7;          // row quarter 0..3 (32 rows each)
    const float b2c = sB2[segc];

    using namespace nvcuda;
    const int warpId = tid >> 5;
    const int wm = warpId >> 2;   // 0..3 (32-row band)
    const int wn = warpId & 3;    // 0..3 (32-col band)

    for (long long tile = blockIdx.x; tile < ntiles; tile += gridDim.x) {
        const long long r0 = tile * TILE;

        __syncthreads();  // prev iteration's segment pass done with sC

        // --- load v tile (128*256 f32, contiguous) -> fp16 sA ---
        {
            const float4* src = (const float4*)(v + r0 * HDIM);
            #pragma unroll
            for (int it = 0; it < 16; ++it) {
                int l4 = it * THREADS + tid;       // float4 index within tile
                int row = l4 >> 6;                 // (l4*4)/256
                int col = (l4 & 63) * 4;
                float4 f = make_float4(0.f, 0.f, 0.f, 0.f);
                if (r0 + row < N) f = src[l4];
                __half* d = &sA[row * LDA + col];
                d[0] = __float2half(f.x); d[1] = __float2half(f.y);
                d[2] = __float2half(f.z); d[3] = __float2half(f.w);
            }
        }
        if (tid < TILE) {
            long long r = r0 + tid;
            int g = -1;
            if (r < N) g = (int)get_batch(batch, r, is64);
            sIdx[tid] = g;
        }
        __syncthreads();

        wmma::fragment<wmma::accumulator, 16, 16, 16, float> acc[2][2];

        // --- GEMM1: C1 = A[128x256] @ W1[256x128] ---
        #pragma unroll
        for (int i = 0; i < 2; ++i)
            #pragma unroll
            for (int j = 0; j < 2; ++j) wmma::fill_fragment(acc[i][j], 0.0f);

        #pragma unroll
        for (int k = 0; k < HDIM / 16; ++k) {
            wmma::fragment<wmma::matrix_a, 16, 16, 16, __half, wmma::row_major> af[2];
            #pragma unroll
            for (int i = 0; i < 2; ++i)
                wmma::load_matrix_sync(af[i], &sA[(wm * 32 + i * 16) * LDA + k * 16], LDA);
            wmma::fragment<wmma::matrix_b, 16, 16, 16, __half, wmma::row_major> bf[2];
            #pragma unroll
            for (int j = 0; j < 2; ++j)
                wmma::load_matrix_sync(bf[j], &sW1[(k * 16) * LDW + wn * 32 + j * 16], LDW);
            #pragma unroll
            for (int i = 0; i < 2; ++i)
                #pragma unroll
                for (int j = 0; j < 2; ++j)
                    wmma::mma_sync(acc[i][j], af[i], bf[j], acc[i][j]);
        }
        __syncthreads();  // all GEMM1 reads of sA done -> buffer reusable as sC

        #pragma unroll
        for (int i = 0; i < 2; ++i)
            #pragma unroll
            for (int j = 0; j < 2; ++j)
                wmma::store_matrix_sync(&sC[(wm * 32 + i * 16) * LDC + wn * 32 + j * 16],
                                        acc[i][j], LDC, wmma::mem_row_major);
        __syncthreads();

        // --- bias + LeakyReLU + f32->f16, in place (reg-staged) ---
        // 8192 half2 elements; col2 = tid&63 constant, row = it*8 + tid>>6.
        {
            float2 rf[16];
            #pragma unroll
            for (int it = 0; it < 16; ++it) {
                int row = it * 8 + (tid >> 6);
                rf[it] = sC2[row * 66 + col2];
            }
            __syncthreads();  // all f32 reads complete before f16 overwrite
            #pragma unroll
            for (int it = 0; it < 16; ++it) {
                int row = it * 8 + (tid >> 6);
                float x = rf[it].x + bb1.x;
                float y = rf[it].y + bb1.y;
                x = (x >= 0.f) ? x : NEG_SLOPE * x;
                y = (y >= 0.f) ? y : NEG_SLOPE * y;
                sH2[row * 132 + col2] = __floats2half2_rn(x, y);
            }
        }
        __syncthreads();

        // --- GEMM2: C2 = H[128x128] @ W2[128x128] ---
        #pragma unroll
        for (int i = 0; i < 2; ++i)
            #pragma unroll
            for (int j = 0; j < 2; ++j) wmma::fill_fragment(acc[i][j], 0.0f);

        #pragma unroll
        for (int k = 0; k < HMID / 16; ++k) {
            wmma::fragment<wmma::matrix_a, 16, 16, 16, __half, wmma::row_major> af[2];
            #pragma unroll
            for (int i = 0; i < 2; ++i)
                wmma::load_matrix_sync(af[i], &sH[(wm * 32 + i * 16) * LDA + k * 16], LDA);
            wmma::fragment<wmma::matrix_b, 16, 16, 16, __half, wmma::row_major> bf[2];
            #pragma unroll
            for (int j = 0; j < 2; ++j)
                wmma::load_matrix_sync(bf[j], &sW2[(k * 16) * LDW + wn * 32 + j * 16], LDW);
            #pragma unroll
            for (int i = 0; i < 2; ++i)
                #pragma unroll
                for (int j = 0; j < 2; ++j)
                    wmma::mma_sync(acc[i][j], af[i], bf[j], acc[i][j]);
        }
        __syncthreads();  // all GEMM2 reads of sH done before f32 overwrite

        #pragma unroll
        for (int i = 0; i < 2; ++i)
            #pragma unroll
            for (int j = 0; j < 2; ++j)
                wmma::store_matrix_sync(&sC[(wm * 32 + i * 16) * LDC + wn * 32 + j * 16],
                                        acc[i][j], LDC, wmma::mem_row_major);
        __syncthreads();

        // --- segment accumulate: run-length compress sorted group ids ---
        // 512 threads: column segc, row quarter segq (32 rows each).
        {
            int rbeg = segq * 32, rend = rbeg + 32;
            int curg = sIdx[rbeg];
            float s = 0.0f;
            for (int i = rbeg; i < rend; ++i) {
                int g = sIdx[i];
                float val = sC[i * LDC + segc] + b2c;
                if (g != curg) {
                    if (curg >= 0) atomicAdd(&out[(long long)curg * ODIM + segc], s);
                    curg = g; s = 0.0f;
                }
                if (g >= 0) s += val;
            }
            if (curg >= 0) atomicAdd(&out[(long long)curg * ODIM + segc], s);
        }
    }
}

// ---------------------------------------------------------------------------
extern "C" void kernel_launch(void* const* d_in, const int* in_sizes, int n_in,
                              void* d_out, int out_size) {
    // metadata order: v, batch, num_graphs, W1, b1, W2, b2
    const float* v     = (const float*)d_in[0];
    const void*  batch = d_in[1];
    const float* W1    = (const float*)d_in[3];
    const float* b1    = (const float*)d_in[4];
    const float* W2    = (const float*)d_in[5];
    const float* b2    = (const float*)d_in[6];
    float* out = (float*)d_out;

    long long N = (long long)in_sizes[1];            // rows
    long long OUT = (long long)out_size;             // G * ODIM
    int G = (int)(OUT / ODIM);
    long long ntiles = (N + TILE - 1) / TILE;

    int dev = 0, nsm = 148;
    cudaGetDevice(&dev);
    cudaDeviceGetAttribute(&nsm, cudaDevAttrMultiProcessorCount, dev);
    long long grid = (ntiles < (long long)nsm) ? ntiles : (long long)nsm;

    cudaFuncSetAttribute(mlp_kernel, cudaFuncAttributeMaxDynamicSharedMemorySize, 196608);

    detect_kernel<<<1, 256>>>((const int*)batch, N);
    counts_kernel<<<(G + 255) / 256, 256>>>(batch, N, G);
    zero_kernel<<<(unsigned)((OUT + 255) / 256), 256>>>(out, OUT);

    mlp_kernel<<<(unsigned)grid, THREADS, SMEM_BYTES>>>(v, batch, W1, b1, W2, b2, out, N, ntiles);

    divide_kernel<<<(unsigned)((OUT + 255) / 256), 256>>>(out, OUT);
}